// round 1
// baseline (speedup 1.0000x reference)
#include <cuda_runtime.h>

// ============================================================================
// AdaptiveTimeFrequency: y[b,f,:] = circular-correlation(x[b], r[f])
//   r[f,m] = softmax(window_params[f])[m] * cos(2*pi*freq_f*m)
//   via FFT: y = ifft( FFT(x) * conj(FFT(r)) )
// Batch-pair packing: FFT(x[2b] + i*x[2b+1]) -> one complex ifft yields two
// real output rows (real part = row 2b, imag part = row 2b+1).
// B=256, F=32, L=4096.
// ============================================================================

#define L_FFT 4096
#define NTHREADS 256
#define F_FILT 32
#define B_BATCH 256
#define BP (B_BATCH / 2)

__device__ float2 g_Zf[BP * L_FFT];      // packed spectra of x row pairs (4 MB)
__device__ float2 g_Rf[F_FILT * L_FFT];  // FFT(r_f) / L   (1 MB)

// ---------------- complex helpers ----------------
__device__ __forceinline__ float2 cadd(float2 a, float2 b) { return make_float2(a.x + b.x, a.y + b.y); }
__device__ __forceinline__ float2 csub(float2 a, float2 b) { return make_float2(a.x - b.x, a.y - b.y); }
__device__ __forceinline__ float2 cmul(float2 a, float2 b) {
    return make_float2(fmaf(a.x, b.x, -a.y * b.y), fmaf(a.x, b.y, a.y * b.x));
}

// 16th roots of unity: cos/sin(2*pi*k/16)
__device__ __constant__ float C16T[16] = {
    1.0f,  0.92387953251128675613f,  0.70710678118654752440f,  0.38268343236508977173f,
    0.0f, -0.38268343236508977173f, -0.70710678118654752440f, -0.92387953251128675613f,
   -1.0f, -0.92387953251128675613f, -0.70710678118654752440f, -0.38268343236508977173f,
    0.0f,  0.38268343236508977173f,  0.70710678118654752440f,  0.92387953251128675613f};
__device__ __constant__ float S16T[16] = {
    0.0f,  0.38268343236508977173f,  0.70710678118654752440f,  0.92387953251128675613f,
    1.0f,  0.92387953251128675613f,  0.70710678118654752440f,  0.38268343236508977173f,
    0.0f, -0.38268343236508977173f, -0.70710678118654752440f, -0.92387953251128675613f,
   -1.0f, -0.92387953251128675613f, -0.70710678118654752440f, -0.38268343236508977173f};

template <int DIR>  // DIR = -1 forward, +1 inverse (unscaled)
__device__ __forceinline__ float2 cmulw16(float2 a, int m) {
    float2 w = make_float2(C16T[m & 15], (float)DIR * S16T[m & 15]);
    return cmul(a, w);
}

// 16-point DFT in registers: out[k] = sum_n in[n] * exp(DIR*2*pi*i*n*k/16)
template <int DIR>
__device__ __forceinline__ void fft16(float2 v[16]) {
    float2 u[16];
#pragma unroll
    for (int q = 0; q < 4; ++q) {
        float2 a = v[q], b = v[q + 4], c = v[q + 8], d = v[q + 12];
        float2 t0 = cadd(a, c), t1 = csub(a, c), t2 = cadd(b, d), t3 = csub(b, d);
        float2 jt3 = make_float2((float)(-DIR) * t3.y, (float)DIR * t3.x);  // DIR*i*t3
        u[4 * q + 0] = cadd(t0, t2);
        u[4 * q + 1] = cadd(t1, jt3);
        u[4 * q + 2] = csub(t0, t2);
        u[4 * q + 3] = csub(t1, jt3);
    }
#pragma unroll
    for (int q = 0; q < 4; ++q) {
        float2 a = u[q];
        float2 b = (q == 0) ? u[q + 4]  : cmulw16<DIR>(u[q + 4], q);
        float2 c = (q == 0) ? u[q + 8]  : cmulw16<DIR>(u[q + 8], 2 * q);
        float2 d = (q == 0) ? u[q + 12] : cmulw16<DIR>(u[q + 12], 3 * q);
        float2 t0 = cadd(a, c), t1 = csub(a, c), t2 = cadd(b, d), t3 = csub(b, d);
        float2 jt3 = make_float2((float)(-DIR) * t3.y, (float)DIR * t3.x);
        v[q]      = cadd(t0, t2);
        v[q + 4]  = cadd(t1, jt3);
        v[q + 8]  = csub(t0, t2);
        v[q + 12] = csub(t1, jt3);
    }
}

// Padded smem index: stride-16 / stride-256 patterns become conflict-free.
__device__ __forceinline__ int pad(int i) { return i + (i >> 4); }
#define SMEM_ELEMS (L_FFT + (L_FFT >> 4))  // 4352

// twiddle chain: v[r] *= exp(i*r*ang), r=1..15 (one sincos + 14 cmuls)
__device__ __forceinline__ void twiddle_chain(float2 v[16], float ang) {
    float sn, cs;
    sincosf(ang, &sn, &cs);
    float2 w1 = make_float2(cs, sn);
    float2 w = w1;
    v[1] = cmul(v[1], w);
#pragma unroll
    for (int r = 2; r < 16; ++r) {
        w = cmul(w, w1);
        v[r] = cmul(v[r], w);
    }
}

// Full 4096-pt FFT, 256 threads. Input: v[r] = in[j + 256*r]. Output: out[j+256*k]=v[k].
template <int DIR>
__device__ __forceinline__ void fft4096(float2 v[16], float2* s, int j) {
    const float TWO_PI = 6.28318530717958647692f;
    // iteration 1: Ns=1 (no twiddle)
    fft16<DIR>(v);
#pragma unroll
    for (int k = 0; k < 16; ++k) s[pad(16 * j + k)] = v[k];
    __syncthreads();
    // iteration 2: Ns=16
    {
#pragma unroll
        for (int r = 0; r < 16; ++r) v[r] = s[pad(j + 256 * r)];
        float ang = (float)DIR * (TWO_PI / 256.0f) * (float)(j & 15);
        twiddle_chain(v, ang);
        fft16<DIR>(v);
        int idxD = (j >> 4) * 256 + (j & 15);
        __syncthreads();
#pragma unroll
        for (int k = 0; k < 16; ++k) s[pad(idxD + 16 * k)] = v[k];
    }
    __syncthreads();
    // iteration 3: Ns=256 -> natural order result in v[k] (index j + 256k)
    {
#pragma unroll
        for (int r = 0; r < 16; ++r) v[r] = s[pad(j + 256 * r)];
        float ang = (float)DIR * (TWO_PI / 4096.0f) * (float)j;
        twiddle_chain(v, ang);
        fft16<DIR>(v);
    }
}

// ---------------- Kernel 1: atoms -> g_Rf (32 CTAs) ----------------
__global__ __launch_bounds__(NTHREADS) void k_fft_r(const float* __restrict__ wp,
                                                    const float* __restrict__ fp) {
    __shared__ float2 s[SMEM_ELEMS];
    __shared__ float red[8];
    int f = blockIdx.x, j = threadIdx.x;
    const float* row = wp + f * L_FFT;

    float w[16];
    float mx = -3.4e38f;
#pragma unroll
    for (int r = 0; r < 16; ++r) {
        w[r] = row[j + 256 * r];
        mx = fmaxf(mx, w[r]);
    }
#pragma unroll
    for (int off = 16; off; off >>= 1) mx = fmaxf(mx, __shfl_xor_sync(0xffffffffu, mx, off));
    if ((j & 31) == 0) red[j >> 5] = mx;
    __syncthreads();
    float bm = red[0];
#pragma unroll
    for (int i = 1; i < 8; ++i) bm = fmaxf(bm, red[i]);
    __syncthreads();

    float se = 0.0f;
#pragma unroll
    for (int r = 0; r < 16; ++r) {
        w[r] = expf(w[r] - bm);
        se += w[r];
    }
#pragma unroll
    for (int off = 16; off; off >>= 1) se += __shfl_xor_sync(0xffffffffu, se, off);
    if ((j & 31) == 0) red[j >> 5] = se;
    __syncthreads();
    float bs = 0.0f;
#pragma unroll
    for (int i = 0; i < 8; ++i) bs += red[i];
    __syncthreads();

    // fold softmax normalization AND the ifft 1/L into the atom
    float scale = 1.0f / (bs * (float)L_FFT);
    float freq = 0.5f / (1.0f + expf(-fp[f]));  // sigmoid * 0.5
    float a = -6.2831853071795864769f * freq;   // matches ref: (-2*pi*freq) in fp32

    float2 v[16];
#pragma unroll
    for (int r = 0; r < 16; ++r) {
        int n = j + 256 * r;
        float ph = a * (float)n;
        v[r] = make_float2(w[r] * scale * cosf(ph), 0.0f);
    }
    fft4096<-1>(v, s, j);
#pragma unroll
    for (int k = 0; k < 16; ++k) g_Rf[f * L_FFT + j + 256 * k] = v[k];
}

// ---------------- Kernel 2: packed forward FFTs of x (128 CTAs) ----------------
__global__ __launch_bounds__(NTHREADS) void k_fft_x(const float* __restrict__ x) {
    __shared__ float2 s[SMEM_ELEMS];
    int bp = blockIdx.x, j = threadIdx.x;
    const float* x1 = x + (size_t)(2 * bp) * L_FFT;
    const float* x2 = x + (size_t)(2 * bp + 1) * L_FFT;

    float2 v[16];
#pragma unroll
    for (int r = 0; r < 16; ++r) {
        int i = j + 256 * r;
        v[r] = make_float2(x1[i], x2[i]);  // FFT(x1 + i*x2) = X1 + i*X2
    }
    fft4096<-1>(v, s, j);
#pragma unroll
    for (int k = 0; k < 16; ++k) g_Zf[bp * L_FFT + j + 256 * k] = v[k];
}

// ---------------- Kernel 3: product + inverse FFT + write (32 x 128 CTAs) -------
__global__ __launch_bounds__(NTHREADS) void k_main(float* __restrict__ out) {
    __shared__ float2 s[SMEM_ELEMS];
    int f = blockIdx.x;
    int bp = blockIdx.y;
    int j = threadIdx.x;

    const float2* __restrict__ Z = g_Zf + (size_t)bp * L_FFT;
    const float2* __restrict__ R = g_Rf + (size_t)f * L_FFT;

    float2 v[16];
#pragma unroll
    for (int r = 0; r < 16; ++r) {
        int i = j + 256 * r;
        float2 z = Z[i];
        float2 rr = R[i];
        // z * conj(rr)  (1/L already folded into rr)
        v[r] = make_float2(fmaf(z.x, rr.x, z.y * rr.y), fmaf(z.y, rr.x, -z.x * rr.y));
    }
    fft4096<1>(v, s, j);  // inverse, unscaled

    float* __restrict__ o1 = out + ((size_t)(2 * bp) * F_FILT + f) * L_FFT;
    float* __restrict__ o2 = out + ((size_t)(2 * bp + 1) * F_FILT + f) * L_FFT;
#pragma unroll
    for (int k = 0; k < 16; ++k) {
        int i = j + 256 * k;
        o1[i] = v[k].x;  // real part -> batch row 2*bp
        o2[i] = v[k].y;  // imag part -> batch row 2*bp+1
    }
}

extern "C" void kernel_launch(void* const* d_in, const int* in_sizes, int n_in,
                              void* d_out, int out_size) {
    (void)in_sizes; (void)n_in; (void)out_size;
    const float* x  = (const float*)d_in[0];
    const float* wp = (const float*)d_in[1];
    const float* fp = (const float*)d_in[2];
    float* out = (float*)d_out;

    k_fft_r<<<F_FILT, NTHREADS>>>(wp, fp);
    k_fft_x<<<BP, NTHREADS>>>(x);
    dim3 grid(F_FILT, BP);
    k_main<<<grid, NTHREADS>>>(out);
}